// round 1
// baseline (speedup 1.0000x reference)
#include <cuda_runtime.h>

#define NSTEPS   730
#define NGRID    8000
#define UHL      15
#define UNR      10          // 730 = 73 * 10, exact
#define NEARZERO 1e-5f

__device__ __forceinline__ float sigmoidf_(float x) {
    return 1.0f / (1.0f + __expf(-x));
}

__global__ __launch_bounds__(128, 1)
void hbv_kernel(const float* __restrict__ xphy,    // [T, G, 3]
                const float* __restrict__ params,  // [T, G, 16]
                float*       __restrict__ out)     // [T, G, 4]
{
    const int g = blockIdx.x * blockDim.x + threadIdx.x;
    if (g >= NGRID) return;

    // ---------------- static parameters (last timestep only) ----------------
    const float* pr = params + ((size_t)(NSTEPS - 1) * NGRID + (size_t)g) * 16;
    float4 r0 = *(const float4*)(pr + 0);
    float4 r1 = *(const float4*)(pr + 4);
    float4 r2 = *(const float4*)(pr + 8);
    float4 r3 = *(const float4*)(pr + 12);

    const float parBETA   = 1.0f   + sigmoidf_(r0.x) * 5.0f;
    const float parFC     = 50.0f  + sigmoidf_(r0.y) * 950.0f;
    const float parK0     = 0.05f  + sigmoidf_(r0.z) * 0.85f;
    const float parK1     = 0.01f  + sigmoidf_(r0.w) * 0.49f;
    const float parK2     = 0.001f + sigmoidf_(r1.x) * 0.199f;
    const float parLP     = 0.2f   + sigmoidf_(r1.y) * 0.8f;
    const float parPERC   =          sigmoidf_(r1.z) * 10.0f;
    const float parUZL    =          sigmoidf_(r1.w) * 100.0f;
    const float parTT     = -2.5f  + sigmoidf_(r2.x) * 5.0f;
    const float parCFMAX  = 0.5f   + sigmoidf_(r2.y) * 9.5f;
    const float parCFR    =          sigmoidf_(r2.z) * 0.1f;
    const float parCWH    =          sigmoidf_(r2.w) * 0.2f;
    const float parBETAET = 0.3f   + sigmoidf_(r3.x) * 4.7f;
    const float parC      =          sigmoidf_(r3.y);
    const float route_a   =          sigmoidf_(r3.z) * 2.9f;
    const float route_b   =          sigmoidf_(r3.w) * 6.5f;

    const float inv_fc     = __fdividef(1.0f, parFC);
    const float inv_lpfc   = __fdividef(1.0f, parLP * parFC);
    const float cfr_cfmax  = parCFR * parCFMAX;

    // ---------------- gamma unit-hydrograph weights (normalization cancels
    // the Gamma(a) * theta^a constant, so no lgamma needed) ----------------
    const float aa     = fmaxf(route_a, 0.0f) + 0.1f;
    const float theta  = fmaxf(route_b, 0.0f) + 0.5f;
    const float am1    = aa - 1.0f;
    const float invth  = __fdividef(1.0f, theta);

    float w[UHL];
    float wsum = 0.0f;
    #pragma unroll
    for (int k = 0; k < UHL; k++) {
        float tk = (float)k + 0.5f;
        float v  = __expf(am1 * __logf(tk) - tk * invth);
        w[k] = v;
        wsum += v;
    }
    const float inv_wsum = __fdividef(1.0f, wsum);
    #pragma unroll
    for (int k = 0; k < UHL; k++) w[k] *= inv_wsum;

    // ---------------- state ----------------
    float SNOWPACK = 0.001f, MELTWATER = 0.001f, SM = 0.001f, SUZ = 0.001f, SLZ = 0.001f;

    // shift-register convolution accumulators (future contributions), 14 each
    float a0[UHL - 1], a1[UHL - 1], a2[UHL - 1];
    #pragma unroll
    for (int j = 0; j < UHL - 1; j++) { a0[j] = 0.0f; a1[j] = 0.0f; a2[j] = 0.0f; }

    // ---------------- prefetch first input block ----------------
    float bx[UNR], bt[UNR], bp[UNR];
    #pragma unroll
    for (int u = 0; u < UNR; u++) {
        size_t idx = ((size_t)u * NGRID + (size_t)g) * 3;
        bx[u] = xphy[idx + 0];
        bt[u] = xphy[idx + 1];
        bp[u] = xphy[idx + 2];
    }

    float4* __restrict__ out4 = (float4*)out;

    for (int tb = 0; tb < NSTEPS; tb += UNR) {
        float cx[UNR], ct[UNR], cp[UNR];
        #pragma unroll
        for (int u = 0; u < UNR; u++) { cx[u] = bx[u]; ct[u] = bt[u]; cp[u] = bp[u]; }

        // issue next block's loads early; they overlap with ~1200 cycles of chain
        if (tb + UNR < NSTEPS) {
            #pragma unroll
            for (int u = 0; u < UNR; u++) {
                size_t idx = ((size_t)(tb + UNR + u) * NGRID + (size_t)g) * 3;
                bx[u] = xphy[idx + 0];
                bt[u] = xphy[idx + 1];
                bp[u] = xphy[idx + 2];
            }
        }

        #pragma unroll
        for (int u = 0; u < UNR; u++) {
            const float P   = cx[u];
            const float Tt  = ct[u];
            const float PET = cp[u];

            // snow partition
            const float RAIN = (Tt >= parTT) ? P : 0.0f;
            const float SNOW = (Tt <  parTT) ? P : 0.0f;
            SNOWPACK += SNOW;
            const float melt = fminf(fmaxf(parCFMAX * (Tt - parTT), 0.0f), SNOWPACK);
            MELTWATER += melt;
            SNOWPACK  -= melt;
            const float refreeze = fminf(fmaxf(cfr_cfmax * (parTT - Tt), 0.0f), MELTWATER);
            SNOWPACK  += refreeze;
            MELTWATER -= refreeze;
            const float tosoil = fmaxf(MELTWATER - parCWH * SNOWPACK, 0.0f);
            MELTWATER -= tosoil;

            // soil moisture (soil_wet uses SM from iteration start -> off snow chain)
            const float soil_wet = fminf(__powf(SM * inv_fc, parBETA), 1.0f);
            const float rt = RAIN + tosoil;
            const float recharge = rt * soil_wet;
            SM = SM + rt - recharge;
            const float excess = fmaxf(SM - parFC, 0.0f);
            SM -= excess;

            // capillary rise
            const float capillary = fminf(SLZ, parC * SLZ * (1.0f - fminf(SM * inv_fc, 1.0f)));
            SM  = fmaxf(SM + capillary, NEARZERO);
            SLZ = fmaxf(SLZ - capillary, NEARZERO);

            // evapotranspiration
            const float evr = fminf(fmaxf(SM * inv_lpfc, 0.0f), 1.0f);
            const float evapfactor = __powf(evr, parBETAET);
            const float ET = fminf(PET * evapfactor, SM);
            SM = fmaxf(SM - ET, NEARZERO);

            // upper / lower zone routing
            SUZ += recharge + excess;
            const float perc = fminf(SUZ, parPERC);
            SUZ -= perc;
            const float Q0 = parK0 * fmaxf(SUZ - parUZL, 0.0f);
            SUZ -= Q0;
            const float Q1 = parK1 * SUZ;
            SUZ -= Q1;
            SLZ += perc;
            const float Q2 = parK2 * SLZ;
            SLZ -= Q2;

            // 15-tap causal convolution via shift-FMA accumulators
            const float y0 = a0[0] + w[0] * Q0;
            const float y1 = a1[0] + w[0] * Q1;
            const float y2 = a2[0] + w[0] * Q2;
            #pragma unroll
            for (int j = 0; j < UHL - 2; j++) {
                a0[j] = a0[j + 1] + w[j + 1] * Q0;
                a1[j] = a1[j + 1] + w[j + 1] * Q1;
                a2[j] = a2[j + 1] + w[j + 1] * Q2;
            }
            a0[UHL - 2] = w[UHL - 1] * Q0;
            a1[UHL - 2] = w[UHL - 1] * Q1;
            a2[UHL - 2] = w[UHL - 1] * Q2;

            // out[t, g, :] = {streamflow, srflow, ssflow, gwflow}
            float4 o;
            o.x = y0 + y1 + y2;
            o.y = y0;
            o.z = y1;
            o.w = y2;
            out4[(size_t)(tb + u) * NGRID + (size_t)g] = o;
        }
    }
}

extern "C" void kernel_launch(void* const* d_in, const int* in_sizes, int n_in,
                              void* d_out, int out_size) {
    const float* xphy   = (const float*)d_in[0];   // [730, 8000, 3]
    const float* params = (const float*)d_in[1];   // [730, 8000, 16]
    float* out = (float*)d_out;                    // [730, 8000, 4]
    (void)in_sizes; (void)n_in; (void)out_size;

    dim3 block(128);
    dim3 grid((NGRID + 127) / 128);
    hbv_kernel<<<grid, block>>>(xphy, params, out);
}